// round 5
// baseline (speedup 1.0000x reference)
#include <cuda_runtime.h>
#include <math.h>

#define TPB 256

// ---------------- scratch (device globals; allocation-free rule) ----------------
__device__ float g_attn[78675968];   // max 2*12544*3136 (stage 3)
__device__ float g_q[802816];        // hr projection, [b][n][h]
__device__ float g_qh[802816];       // hr projection, [b][h][n]
__device__ float g_kv[200704];       // lr projection, [b][n][h]
__device__ float g_kvh[200704];      // lr projection, [b][h][n]
__device__ float g_x1[100352];       // CSA1 out  [2,784,64]   channel-last
__device__ float g_x2[401408];       // CSA2 out  [2,3136,64]
__device__ float g_x3[802816];       // CSA3 out  [2,12544,32]
__device__ float g_y1[200704];       // msr1 out  [2,3136,32]
__device__ float g_y2[401408];       // msr2 out  [2,12544,16]
__device__ float g_y3[802816];       // msr3 out  [2,50176,8]
__device__ float g_mb[19208];        // per-tile max   (max 2*196*49)
__device__ float g_sb[19208];        // per-tile sumexp
__device__ float g_Ms[2];
__device__ float g_invS[2];

// ---------------- f32x2 packed helpers (Blackwell FFMA2) ----------------
typedef unsigned long long u64;

__device__ __forceinline__ u64 pk2(float x) {
    u64 r;
    asm("mov.b64 %0, {%1, %1};" : "=l"(r) : "r"(__float_as_uint(x)));
    return r;
}
__device__ __forceinline__ void fma2(u64& d, u64 a, u64 b) {
    asm("fma.rn.f32x2 %0, %1, %2, %0;" : "+l"(d) : "l"(a), "l"(b));
}
__device__ __forceinline__ float2 upk2(u64 v) {
    unsigned int lo, hi;
    asm("mov.b64 {%0, %1}, %2;" : "=r"(lo), "=r"(hi) : "l"(v));
    return make_float2(__uint_as_float(lo), __uint_as_float(hi));
}

// ---------------- cp.async helpers ----------------
__device__ __forceinline__ void cpa16(float* smem_dst, const float* gsrc, int szbytes) {
    unsigned saddr = (unsigned)__cvta_generic_to_shared(smem_dst);
    asm volatile("cp.async.ca.shared.global [%0], [%1], 16, %2;"
                 :: "r"(saddr), "l"(gsrc), "r"(szbytes));
}
__device__ __forceinline__ void cp_commit() {
    asm volatile("cp.async.commit_group;");
}
template<int N> __device__ __forceinline__ void cp_wait() {
    asm volatile("cp.async.wait_group %0;" :: "n"(N));
}

// ---------------- block reductions (warp shuffle + 1 cross-warp pass) ----------------
__device__ __forceinline__ float block_max(float v, float* warpbuf, int tid) {
#pragma unroll
    for (int o = 16; o; o >>= 1) v = fmaxf(v, __shfl_xor_sync(0xffffffffu, v, o));
    if ((tid & 31) == 0) warpbuf[tid >> 5] = v;
    __syncthreads();
    float r = warpbuf[tid & 7];
#pragma unroll
    for (int o = 4; o; o >>= 1) r = fmaxf(r, __shfl_xor_sync(0xffffffffu, r, o));
    __syncthreads();
    return r;
}
__device__ __forceinline__ float block_sum(float v, float* warpbuf, int tid) {
#pragma unroll
    for (int o = 16; o; o >>= 1) v += __shfl_xor_sync(0xffffffffu, v, o);
    if ((tid & 31) == 0) warpbuf[tid >> 5] = v;
    __syncthreads();
    float r = warpbuf[tid & 7];
#pragma unroll
    for (int o = 4; o; o >>= 1) r += __shfl_xor_sync(0xffffffffu, r, o);
    __syncthreads();
    return r;
}

// ---------------- projection: out[b,n,h] (+ out_hn[b,h,n]) = sum_c A * W ----------------
// CHLAST=false: A is NCHW (A[b][c][n]); CHLAST=true: A is [b][n][c].
template<bool CHLAST>
__global__ void proj_kernel(const float* __restrict__ A, const float* __restrict__ W,
                            float* __restrict__ out, float* __restrict__ out_hn,
                            int N, int C, int H)
{
    __shared__ float sW[64 * 64];
    __shared__ float sA[64 * 65];
    const int b  = blockIdx.y;
    const int n0 = blockIdx.x * 64;
    const int tid = threadIdx.x;

    float acc[16];
#pragma unroll
    for (int i = 0; i < 16; i++) acc[i] = 0.f;

    for (int c0 = 0; c0 < C; c0 += 64) {
        const int CC = min(64, C - c0);
        for (int i = tid; i < CC * H; i += TPB)
            sW[i] = W[(size_t)(c0 + i / H) * H + (i % H)];
        for (int i = tid; i < 64 * CC; i += TPB) {
            int n, c;
            if (CHLAST) { n = i / CC; c = i % CC; }
            else        { c = i / 64; n = i % 64; }
            int nn = n0 + n;
            float v = 0.f;
            if (nn < N)
                v = CHLAST ? A[((size_t)b * N + nn) * C + c0 + c]
                           : A[((size_t)b * C + c0 + c) * N + nn];
            sA[n * 65 + c] = v;
        }
        __syncthreads();
        int k = 0;
        for (int o = tid; o < 64 * H; o += TPB, k++) {
            int n = o / H, h = o % H;
            float s = acc[k];
            for (int c = 0; c < CC; c++)
                s += sA[n * 65 + c] * sW[c * H + h];
            acc[k] = s;
        }
        __syncthreads();
    }
    int k = 0;
    for (int o = tid; o < 64 * H; o += TPB, k++) {
        int n = o / H, h = o % H;
        int nn = n0 + n;
        if (nn < N) {
            out[((size_t)b * N + nn) * H + h]    = acc[k];
            out_hn[((size_t)b * H + h) * N + nn] = acc[k];
        }
    }
}

// ---------------- pass A: attn tile = Q @ K^T, store exp(a - m_b), emit (m_b, s_b) ----------------
// Qhn/Khn are [b][h][n]. Tiles staged k-major (s[k][n], pitch 68): conflict-free
// STS + coalesced global loads. Inner loop: row-pair operands come free as
// ulonglong2; 4 broadcast packs + 8 FFMA2 per k-step.
template<int H>
__global__ void attn_passA(const float* __restrict__ Qhn, const float* __restrict__ Khn,
                           float* __restrict__ attn,
                           float* __restrict__ mb, float* __restrict__ sb,
                           int N1, int N2)
{
    constexpr int P = 68;                 // 272B rows, 16B-aligned subtiles
    __shared__ float sbuf[2 * H * P];     // sQ | sK ; also >= 64*65 staging
    __shared__ float warpbuf[8];
    float* sQ = sbuf;
    float* sK = sbuf + H * P;
    const int b  = blockIdx.z;
    const int n0 = blockIdx.y * 64, m0 = blockIdx.x * 64;
    const int tid = threadIdx.x;
    const int ty = tid >> 4, tx = tid & 15;    // rows 4*ty.., cols 4*tx..
    const bool full = (n0 + 64 <= N1) && (m0 + 64 <= N2);

    for (int i = tid; i < 64 * H; i += TPB) {
        int c = i >> 6, n = i & 63;        // consecutive tid -> consecutive n
        sQ[c * P + n] = (n0 + n < N1) ? Qhn[((size_t)b * H + c) * N1 + n0 + n] : 0.f;
        sK[c * P + n] = (m0 + n < N2) ? Khn[((size_t)b * H + c) * N2 + m0 + n] : 0.f;
    }
    __syncthreads();

    u64 acc01[4], acc23[4];                // rows (4ty+0,1) and (4ty+2,3) x cols 4tx+j
#pragma unroll
    for (int j = 0; j < 4; j++) { acc01[j] = 0ull; acc23[j] = 0ull; }

#pragma unroll 4
    for (int k = 0; k < H; k++) {
        const ulonglong2 ap = *(const ulonglong2*)(sQ + k * P + 4 * ty);
        const float4    bv = *(const float4*)(sK + k * P + 4 * tx);
        const u64 bd[4] = { pk2(bv.x), pk2(bv.y), pk2(bv.z), pk2(bv.w) };
#pragma unroll
        for (int j = 0; j < 4; j++) { fma2(acc01[j], ap.x, bd[j]); fma2(acc23[j], ap.y, bd[j]); }
    }

    float acc[4][4];
#pragma unroll
    for (int j = 0; j < 4; j++) {
        float2 lo = upk2(acc01[j]), hi = upk2(acc23[j]);
        acc[0][j] = lo.x; acc[1][j] = lo.y; acc[2][j] = hi.x; acc[3][j] = hi.y;
    }

    // block max over valid elements (fast path: fully interior tile)
    float lm = -1e30f;
    if (full) {
#pragma unroll
        for (int i = 0; i < 4; i++)
#pragma unroll
            for (int j = 0; j < 4; j++) lm = fmaxf(lm, acc[i][j]);
    } else {
#pragma unroll
        for (int i = 0; i < 4; i++)
#pragma unroll
            for (int j = 0; j < 4; j++)
                if (n0 + 4 * ty + i < N1 && m0 + 4 * tx + j < N2)
                    lm = fmaxf(lm, acc[i][j]);
    }
    const float bm = block_max(lm, warpbuf, tid);

    // exp and block sum
    float ls = 0.f;
    if (full) {
#pragma unroll
        for (int i = 0; i < 4; i++)
#pragma unroll
            for (int j = 0; j < 4; j++) {
                float p = __expf(acc[i][j] - bm);
                acc[i][j] = p;
                ls += p;
            }
    } else {
#pragma unroll
        for (int i = 0; i < 4; i++)
#pragma unroll
            for (int j = 0; j < 4; j++)
                if (n0 + 4 * ty + i < N1 && m0 + 4 * tx + j < N2) {
                    float p = __expf(acc[i][j] - bm);
                    acc[i][j] = p;
                    ls += p;
                }
    }
    const float bs = block_sum(ls, warpbuf, tid);
    if (tid == 0) {
        int idx = (b * gridDim.y + blockIdx.y) * gridDim.x + blockIdx.x;
        mb[idx] = bm; sb[idx] = bs;
    }

    // stage tile in smem (sbuf reused; 64*65 <= 2*H*P), write coalesced
#pragma unroll
    for (int i = 0; i < 4; i++)
#pragma unroll
        for (int j = 0; j < 4; j++)
            sbuf[(4 * ty + i) * 65 + 4 * tx + j] = acc[i][j];
    __syncthreads();
    if (full) {
        for (int i = tid; i < 64 * 64; i += TPB) {
            int r = i >> 6, m = i & 63;
            attn[((size_t)b * N1 + n0 + r) * N2 + m0 + m] = sbuf[r * 65 + m];
        }
    } else {
        for (int i = tid; i < 64 * 64; i += TPB) {
            int r = i >> 6, m = i & 63;
            int n = n0 + r, mm = m0 + m;
            if (n < N1 && mm < N2)
                attn[((size_t)b * N1 + n) * N2 + mm] = sbuf[r * 65 + m];
        }
    }
}

// ---------------- combine per-tile partials into global (M, 1/S) per batch ----------------
__global__ void softmax_reduce(const float* __restrict__ mb, const float* __restrict__ sb,
                               float* __restrict__ Ms, float* __restrict__ invS, int nb)
{
    __shared__ float red[TPB];
    const int b = blockIdx.x, tid = threadIdx.x;
    float lm = -1e30f;
    for (int i = tid; i < nb; i += TPB) lm = fmaxf(lm, mb[b * nb + i]);
    red[tid] = lm; __syncthreads();
    for (int s = 128; s; s >>= 1) { if (tid < s) red[tid] = fmaxf(red[tid], red[tid + s]); __syncthreads(); }
    const float M = red[0]; __syncthreads();
    float ls = 0.f;
    for (int i = tid; i < nb; i += TPB) ls += sb[b * nb + i] * __expf(mb[b * nb + i] - M);
    red[tid] = ls; __syncthreads();
    for (int s = 128; s; s >>= 1) { if (tid < s) red[tid] += red[tid + s]; __syncthreads(); }
    if (tid == 0) { Ms[b] = M; invS[b] = 1.f / red[0]; }
}

// ---------------- pass B: out = softmax(attn) @ K + Q ----------------
// Double-buffered cp.async pipeline: tile jc+1 streams into the alternate smem
// buffer while tile jc computes. Tiles accumulated RAW into per-tile FFMA2
// accumulators; the per-tile softmax scale sc folds in at tile end (2R fma2).
// sP row-major [n][68] (16B-aligned rows for cp.async, conflict-free reads);
// sK row-major [m][H+4] so col-pairs for FFMA2 come free as ulonglong2.
template<int H>
__global__ void attn_passB(const float* __restrict__ attn, const float* __restrict__ K,
                           const float* __restrict__ Q, float* __restrict__ out,
                           const float* __restrict__ mb, const float* __restrict__ Ms,
                           const float* __restrict__ invS,
                           int N1, int N2, int nb2)
{
    constexpr int TX = H / 4;
    constexpr int TY = TPB / TX;
    constexpr int R  = 64 / TY;
    constexpr int PK = H + 4;
    constexpr int SPSZ = 64 * 68;
    constexpr int SKSZ = 64 * PK;
    extern __shared__ float dynB[];
    float* sPb = dynB;                 // 2 buffers of 64*68
    float* sKb = dynB + 2 * SPSZ;      // 2 buffers of 64*PK
    const int b  = blockIdx.y;
    const int n0 = blockIdx.x * 64;
    const int tid = threadIdx.x;
    const int ty = tid / TX, tx = tid % TX;
    const float M = Ms[b], iS = invS[b];

    u64 accA[R], accB[R];              // row ty*R+r, col pairs (4tx+0,1) / (4tx+2,3)
#pragma unroll
    for (int r = 0; r < R; r++) { accA[r] = 0ull; accB[r] = 0ull; }

    auto issue_tile = [&](int jc, int buf) {
        const int m0 = jc * 64;
        float* sP = sPb + buf * SPSZ;
        float* sK = sKb + buf * SKSZ;
        // attn tile: 64 rows x 64 cols -> 1024 16B copies
        for (int i = tid; i < 1024; i += TPB) {
            int r = i >> 4, mq = (i & 15) * 4;
            int n = n0 + r, mm = m0 + mq;
            bool v = (n < N1) && (mm < N2);      // N2 % 4 == 0 so mm valid => mm+3 valid
            const float* src = attn + ((size_t)b * N1 + (v ? n : 0)) * N2 + (v ? mm : 0);
            cpa16(sP + r * 68 + mq, src, v ? 16 : 0);
        }
        // K tile: 64 rows x H cols -> 16*H 16B copies
        for (int i = tid; i < 16 * H; i += TPB) {
            int r = i / (H / 4), cq = (i % (H / 4)) * 4;
            bool v = (m0 + r) < N2;
            const float* src = K + ((size_t)b * N2 + (v ? m0 + r : 0)) * H + cq;
            cpa16(sK + r * PK + cq, src, v ? 16 : 0);
        }
        cp_commit();
    };

    issue_tile(0, 0);
    for (int jc = 0; jc < nb2; jc++) {
        const int buf = jc & 1;
        if (jc + 1 < nb2) { issue_tile(jc + 1, buf ^ 1); cp_wait<1>(); }
        else              { cp_wait<0>(); }
        __syncthreads();

        const float* sP = sPb + buf * SPSZ;
        const float* sK = sKb + buf * SKSZ;
        u64 tA[R], tB[R];
#pragma unroll
        for (int r = 0; r < R; r++) { tA[r] = 0ull; tB[r] = 0ull; }
#pragma unroll 2
        for (int m = 0; m < 64; m++) {
            const ulonglong2 bp = *(const ulonglong2*)(sK + m * PK + 4 * tx);
#pragma unroll
            for (int r = 0; r < R; r++) {
                const u64 pa = pk2(sP[(ty * R + r) * 68 + m]);
                fma2(tA[r], pa, bp.x);
                fma2(tB[r], pa, bp.y);
            }
        }
        const u64 scp = pk2(__expf(mb[(b * gridDim.x + blockIdx.x) * nb2 + jc] - M) * iS);
#pragma unroll
        for (int r = 0; r < R; r++) { fma2(accA[r], scp, tA[r]); fma2(accB[r], scp, tB[r]); }
        __syncthreads();
    }
#pragma unroll
    for (int r = 0; r < R; r++) {
        int n = n0 + ty * R + r;
        if (n < N1) {
            const size_t base = ((size_t)b * N1 + n) * H + 4 * tx;
            const float4 qv = *(const float4*)(Q + base);
            const float2 lo = upk2(accA[r]), hi = upk2(accB[r]);
            float4 ov;
            ov.x = lo.x + qv.x;
            ov.y = lo.y + qv.y;
            ov.z = hi.x + qv.z;
            ov.w = hi.y + qv.w;
            *(float4*)(out + base) = ov;
        }
    }
}

// ---------------- fused up2(bilinear, half-pixel, edge-clamped) + add + MLP(ReLU6) ----------------
__device__ __forceinline__ float bilin(const float* __restrict__ U, int HI, int WI, int C,
                                       int oy, int ox, int c)
{
    float sy = 0.5f * oy - 0.25f, sx = 0.5f * ox - 0.25f;
    int iy = (int)floorf(sy), ix = (int)floorf(sx);
    float fy = sy - iy, fx = sx - ix;
    int y0 = min(max(iy, 0), HI - 1), y1 = min(max(iy + 1, 0), HI - 1);
    int x0 = min(max(ix, 0), WI - 1), x1 = min(max(ix + 1, 0), WI - 1);
    float v00 = U[((size_t)y0 * WI + x0) * C + c];
    float v01 = U[((size_t)y0 * WI + x1) * C + c];
    float v10 = U[((size_t)y1 * WI + x0) * C + c];
    float v11 = U[((size_t)y1 * WI + x1) * C + c];
    return (1.f - fy) * ((1.f - fx) * v00 + fx * v01) + fy * ((1.f - fx) * v10 + fx * v11);
}

template<int CIN, int CHID, int COUT, bool HB>
__global__ void msr_kernel(const float* __restrict__ base, const float* __restrict__ up,
                           const float* __restrict__ w1, const float* __restrict__ b1,
                           const float* __restrict__ w2, const float* __restrict__ b2,
                           float* __restrict__ out, int HO, int WO)
{
    extern __shared__ float dyn[];
    float* sIn  = dyn;
    float* sHid = sIn  + 64 * (CIN + 1);
    float* sW1  = sHid + 64 * (CHID + 1);
    float* sW2  = sW1  + CIN * CHID;
    float* sB1  = sW2  + CHID * COUT;
    float* sB2  = sB1  + CHID;
    const int b   = blockIdx.y;
    const int p0  = blockIdx.x * 64;
    const int tid = threadIdx.x;
    const int HI = HO / 2, WI = WO / 2;
    for (int i = tid; i < CIN * CHID;  i += TPB) sW1[i] = w1[i];
    for (int i = tid; i < CHID * COUT; i += TPB) sW2[i] = w2[i];
    for (int i = tid; i < CHID; i += TPB) sB1[i] = b1[i];
    for (int i = tid; i < COUT; i += TPB) sB2[i] = b2[i];
    const float* U = up + (size_t)b * HI * WI * CIN;
    for (int i = tid; i < 64 * CIN; i += TPB) {
        int px = i / CIN, c = i % CIN;
        int p = p0 + px, oy = p / WO, ox = p % WO;
        float v = bilin(U, HI, WI, CIN, oy, ox, c);
        if (HB) v += base[((size_t)b * HO * WO + p) * CIN + c];
        sIn[px * (CIN + 1) + c] = v;
    }
    __syncthreads();
    for (int o = tid; o < 64 * CHID; o += TPB) {
        int px = o / CHID, h = o % CHID;
        float s = sB1[h];
#pragma unroll
        for (int c = 0; c < CIN; c++) s += sIn[px * (CIN + 1) + c] * sW1[c * CHID + h];
        sHid[px * (CHID + 1) + h] = fminf(fmaxf(s, 0.f), 6.f);
    }
    __syncthreads();
    for (int o = tid; o < 64 * COUT; o += TPB) {
        int px = o / COUT, h = o % COUT;
        float s = sB2[h];
#pragma unroll
        for (int c = 0; c < CHID; c++) s += sHid[px * (CHID + 1) + c] * sW2[c * COUT + h];
        out[((size_t)b * HO * WO + p0 + px) * COUT + h] = s;
    }
}

template<int CIN, int CHID, int COUT, bool HB>
static void launch_msr(const float* base, const float* up,
                       const float* w1, const float* b1,
                       const float* w2, const float* b2,
                       float* out, int HO, int WO)
{
    size_t smem = (size_t)(64 * (CIN + 1) + 64 * (CHID + 1) +
                           CIN * CHID + CHID * COUT + CHID + COUT) * sizeof(float);
    cudaFuncSetAttribute(msr_kernel<CIN, CHID, COUT, HB>,
                         cudaFuncAttributeMaxDynamicSharedMemorySize, (int)smem);
    dim3 grid(HO * WO / 64, 2);
    msr_kernel<CIN, CHID, COUT, HB><<<grid, TPB, smem>>>(base, up, w1, b1, w2, b2, out, HO, WO);
}

// ---------------- one CSA stage ----------------
template<int H>
static void run_csa(const float* q_nh, const float* q_hn,
                    const float* k_nh, const float* k_hn, float* outcl,
                    float* attn, float* mb, float* sb, float* Ms, float* invS,
                    int N1, int N2)
{
    int nb1 = (N1 + 63) / 64, nb2 = (N2 + 63) / 64;
    attn_passA<H><<<dim3(nb2, nb1, 2), TPB>>>(q_hn, k_hn, attn, mb, sb, N1, N2);
    softmax_reduce<<<2, TPB>>>(mb, sb, Ms, invS, nb1 * nb2);
    size_t smemB = (size_t)(2 * 64 * 68 + 2 * 64 * (H + 4)) * sizeof(float);
    cudaFuncSetAttribute(attn_passB<H>,
                         cudaFuncAttributeMaxDynamicSharedMemorySize, (int)smemB);
    attn_passB<H><<<dim3(nb1, 2), TPB, smemB>>>(attn, k_nh, q_nh, outcl, mb, Ms, invS, N1, N2, nb2);
}

extern "C" void kernel_launch(void* const* d_in, const int* in_sizes, int n_in,
                              void* d_out, int out_size)
{
    const float* f0   = (const float*)d_in[0];
    const float* f1   = (const float*)d_in[1];
    const float* f2   = (const float*)d_in[2];
    const float* f3   = (const float*)d_in[3];
    const float* c1w1 = (const float*)d_in[4];
    const float* c1w2 = (const float*)d_in[5];
    const float* c2w1 = (const float*)d_in[6];
    const float* c2w2 = (const float*)d_in[7];
    const float* c3w1 = (const float*)d_in[8];
    const float* c3w2 = (const float*)d_in[9];
    const float* m1w1 = (const float*)d_in[10];
    const float* m1b1 = (const float*)d_in[11];
    const float* m1w2 = (const float*)d_in[12];
    const float* m1b2 = (const float*)d_in[13];
    const float* m2w1 = (const float*)d_in[14];
    const float* m2b1 = (const float*)d_in[15];
    const float* m2w2 = (const float*)d_in[16];
    const float* m2b2 = (const float*)d_in[17];
    const float* m3w1 = (const float*)d_in[18];
    const float* m3b1 = (const float*)d_in[19];
    const float* m3w2 = (const float*)d_in[20];
    const float* m3b2 = (const float*)d_in[21];
    const float* m4w1 = (const float*)d_in[22];
    const float* m4b1 = (const float*)d_in[23];
    const float* m4w2 = (const float*)d_in[24];
    const float* m4b2 = (const float*)d_in[25];
    float* outp = (float*)d_out;

    float *attn, *q, *qh, *kv, *kvh, *x1, *x2, *x3, *y1, *y2, *y3, *mb, *sb, *Ms, *invS;
    cudaGetSymbolAddress((void**)&attn, g_attn);
    cudaGetSymbolAddress((void**)&q,    g_q);
    cudaGetSymbolAddress((void**)&qh,   g_qh);
    cudaGetSymbolAddress((void**)&kv,   g_kv);
    cudaGetSymbolAddress((void**)&kvh,  g_kvh);
    cudaGetSymbolAddress((void**)&x1,   g_x1);
    cudaGetSymbolAddress((void**)&x2,   g_x2);
    cudaGetSymbolAddress((void**)&x3,   g_x3);
    cudaGetSymbolAddress((void**)&y1,   g_y1);
    cudaGetSymbolAddress((void**)&y2,   g_y2);
    cudaGetSymbolAddress((void**)&y3,   g_y3);
    cudaGetSymbolAddress((void**)&mb,   g_mb);
    cudaGetSymbolAddress((void**)&sb,   g_sb);
    cudaGetSymbolAddress((void**)&Ms,   g_Ms);
    cudaGetSymbolAddress((void**)&invS, g_invS);

    // ---- CSA stage 1: hr=f1 [2,128,28,28] N1=784, lr=f0 [2,160,14,14] N2=196, H=64
    proj_kernel<false><<<dim3(13, 2), TPB>>>(f1, c1w1, q,  qh,  784, 128, 64);
    proj_kernel<false><<<dim3(4,  2), TPB>>>(f0, c1w2, kv, kvh, 196, 160, 64);
    run_csa<64>(q, qh, kv, kvh, x1, attn, mb, sb, Ms, invS, 784, 196);

    // ---- CSA stage 2: hr=f2 [2,64,56,56] N1=3136, lr=x1 [2,784,64] N2=784, H=64
    proj_kernel<false><<<dim3(49, 2), TPB>>>(f2, c2w1, q,  qh,  3136, 64, 64);
    proj_kernel<true ><<<dim3(13, 2), TPB>>>(x1, c2w2, kv, kvh, 784,  64, 64);
    run_csa<64>(q, qh, kv, kvh, x2, attn, mb, sb, Ms, invS, 3136, 784);

    // ---- CSA stage 3: hr=f3 [2,32,112,112] N1=12544, lr=x2 [2,3136,64] N2=3136, H=32
    proj_kernel<false><<<dim3(196, 2), TPB>>>(f3, c3w1, q,  qh,  12544, 32, 32);
    proj_kernel<true ><<<dim3(49,  2), TPB>>>(x2, c3w2, kv, kvh, 3136,  64, 32);
    run_csa<32>(q, qh, kv, kvh, x3, attn, mb, sb, Ms, invS, 12544, 3136);

    // ---- MSR pyramid (fused up2 + add + MLP/ReLU6), all channel-last
    launch_msr<64, 64, 32, true >(x2, x1, m1w1, m1b1, m1w2, m1b2, y1,  56,  56);
    launch_msr<32, 32, 16, true >(x3, y1, m2w1, m2b1, m2w2, m2b2, y2, 112, 112);
    launch_msr<16, 16, 8,  false>(0,  y2, m3w1, m3b1, m3w2, m3b2, y3, 224, 224);
    launch_msr<8,  2,  1,  false>(0,  y3, m4w1, m4b1, m4w2, m4b2, outp, 448, 448);
    (void)in_sizes; (void)n_in; (void)out_size;
}

// round 9
// speedup vs baseline: 1.6212x; 1.6212x over previous
#include <cuda_runtime.h>
#include <math.h>

#define TPB 256

// ---------------- scratch (device globals; allocation-free rule) ----------------
__device__ float g_attn[78675968];   // max 2*12544*3136 (stage 3), tf32-rounded exp values
__device__ float g_q[802816];        // hr projection, [b][n][h] fp32 (epilogue add)
__device__ float g_qt[802816];       // hr projection, tf32-rounded
__device__ float g_kv[200704];       // lr projection, fp32
__device__ float g_kvt[200704];      // lr projection, tf32-rounded
__device__ float g_x1[100352];       // CSA1 out  [2,784,64]   channel-last fp32
__device__ float g_x2[401408];       // CSA2 out  [2,3136,64]
__device__ float g_x3[802816];       // CSA3 out  [2,12544,32]
__device__ float g_y1[200704];       // msr1 out  [2,3136,32]
__device__ float g_y2[401408];       // msr2 out  [2,12544,16]
__device__ float g_y3[802816];       // msr3 out  [2,50176,8]
__device__ float g_mb[19208];        // per-tile max   (max 2*196*49)
__device__ float g_sb[19208];        // per-tile sumexp
__device__ float g_Ms[2];
__device__ float g_invS[2];

// ---------------- tf32 mma helpers ----------------
__device__ __forceinline__ float to_tf32(float x) {
    float r; asm("cvt.rna.tf32.f32 %0, %1;" : "=f"(r) : "f"(x)); return r;
}
__device__ __forceinline__ void mma_tf32(float d[4], const unsigned a[4], const unsigned b[2]) {
    asm volatile("mma.sync.aligned.m16n8k8.row.col.f32.tf32.tf32.f32 "
                 "{%0,%1,%2,%3}, {%4,%5,%6,%7}, {%8,%9}, {%0,%1,%2,%3};"
                 : "+f"(d[0]), "+f"(d[1]), "+f"(d[2]), "+f"(d[3])
                 : "r"(a[0]), "r"(a[1]), "r"(a[2]), "r"(a[3]), "r"(b[0]), "r"(b[1]));
}

// ---------------- cp.async helpers ----------------
__device__ __forceinline__ void cpa16(float* smem_dst, const float* gsrc, int szbytes) {
    unsigned saddr = (unsigned)__cvta_generic_to_shared(smem_dst);
    asm volatile("cp.async.ca.shared.global [%0], [%1], 16, %2;"
                 :: "r"(saddr), "l"(gsrc), "r"(szbytes));
}
__device__ __forceinline__ void cp_commit() { asm volatile("cp.async.commit_group;"); }
template<int N> __device__ __forceinline__ void cp_wait() {
    asm volatile("cp.async.wait_group %0;" :: "n"(N));
}

// ---------------- block reductions (warp shuffle + 1 cross-warp pass) ----------------
__device__ __forceinline__ float block_max(float v, float* warpbuf, int tid) {
#pragma unroll
    for (int o = 16; o; o >>= 1) v = fmaxf(v, __shfl_xor_sync(0xffffffffu, v, o));
    if ((tid & 31) == 0) warpbuf[tid >> 5] = v;
    __syncthreads();
    float r = warpbuf[tid & 7];
#pragma unroll
    for (int o = 4; o; o >>= 1) r = fmaxf(r, __shfl_xor_sync(0xffffffffu, r, o));
    __syncthreads();
    return r;
}
__device__ __forceinline__ float block_sum(float v, float* warpbuf, int tid) {
#pragma unroll
    for (int o = 16; o; o >>= 1) v += __shfl_xor_sync(0xffffffffu, v, o);
    if ((tid & 31) == 0) warpbuf[tid >> 5] = v;
    __syncthreads();
    float r = warpbuf[tid & 7];
#pragma unroll
    for (int o = 4; o; o >>= 1) r += __shfl_xor_sync(0xffffffffu, r, o);
    __syncthreads();
    return r;
}

// ---------------- projection: out/out_t[b,n,h] = sum_c A * W ----------------
// CHLAST=false: A is NCHW (A[b][c][n]); CHLAST=true: A is [b][n][c].
template<bool CHLAST>
__global__ void __launch_bounds__(TPB)
proj_kernel(const float* __restrict__ A, const float* __restrict__ W,
            float* __restrict__ out, float* __restrict__ out_t,
            int N, int C, int H)
{
    __shared__ float sW[64 * 64];
    __shared__ float sA[64 * 65];
    const int b  = blockIdx.y;
    const int n0 = blockIdx.x * 64;
    const int tid = threadIdx.x;

    float acc[16];
#pragma unroll
    for (int i = 0; i < 16; i++) acc[i] = 0.f;

    for (int c0 = 0; c0 < C; c0 += 64) {
        const int CC = min(64, C - c0);
        for (int i = tid; i < CC * H; i += TPB)
            sW[i] = W[(size_t)(c0 + i / H) * H + (i % H)];
        for (int i = tid; i < 64 * CC; i += TPB) {
            int n, c;
            if (CHLAST) { n = i / CC; c = i % CC; }
            else        { c = i / 64; n = i % 64; }
            int nn = n0 + n;
            float v = 0.f;
            if (nn < N)
                v = CHLAST ? A[((size_t)b * N + nn) * C + c0 + c]
                           : A[((size_t)b * C + c0 + c) * N + nn];
            sA[n * 65 + c] = v;
        }
        __syncthreads();
        int k = 0;
        for (int o = tid; o < 64 * H; o += TPB, k++) {
            int n = o / H, h = o % H;
            float s = acc[k];
            for (int c = 0; c < CC; c++)
                s += sA[n * 65 + c] * sW[c * H + h];
            acc[k] = s;
        }
        __syncthreads();
    }
    int k = 0;
    for (int o = tid; o < 64 * H; o += TPB, k++) {
        int n = o / H, h = o % H;
        int nn = n0 + n;
        if (nn < N) {
            out  [((size_t)b * N + nn) * H + h] = acc[k];
            out_t[((size_t)b * N + nn) * H + h] = to_tf32(acc[k]);
        }
    }
}

// ---------------- pass A: attn tile = Q @ K^T (tf32 mma), store tf32(exp(a-m_b)) ----------------
// Qt/Kt are [b][n][h] tf32-rounded. 8 warps: warp tile 16n x 32m of the 64x64 block tile.
// smem pitch H+4 => fragment LDS bank = (4*g + t) mod 32 : conflict-free.
template<int H>
__global__ void __launch_bounds__(TPB)
attn_passA(const float* __restrict__ Qt, const float* __restrict__ Kt,
           float* __restrict__ attn,
           float* __restrict__ mb, float* __restrict__ sb,
           int N1, int N2)
{
    constexpr int PK = H + 4;
    __shared__ float smem[2 * 64 * PK];   // sQ | sK; reused as 64x65 staging for output
    __shared__ float warpbuf[8];
    float* sQ = smem;
    float* sK = smem + 64 * PK;
    const int b  = blockIdx.z;
    const int n0 = blockIdx.y * 64, m0 = blockIdx.x * 64;
    const int tid = threadIdx.x;
    const int w = tid >> 5, lane = tid & 31;
    const int g = lane >> 2, t = lane & 3;
    const int nw = (w >> 1) * 16, mw = (w & 1) * 32;
    const bool full = (n0 + 64 <= N1) && (m0 + 64 <= N2);

    // stage Q,K tiles [64][H] row-major, zero-padded rows
    for (int i = tid; i < 16 * H; i += TPB) {
        int r = i / (H / 4), q4 = (i % (H / 4)) * 4;
        bool vq = (n0 + r) < N1;
        cpa16(sQ + r * PK + q4, Qt + ((size_t)b * N1 + (vq ? n0 + r : 0)) * H + q4, vq ? 16 : 0);
        bool vk = (m0 + r) < N2;
        cpa16(sK + r * PK + q4, Kt + ((size_t)b * N2 + (vk ? m0 + r : 0)) * H + q4, vk ? 16 : 0);
    }
    cp_commit(); cp_wait<0>();
    __syncthreads();

    float d[4][4];
#pragma unroll
    for (int f = 0; f < 4; f++)
#pragma unroll
        for (int j = 0; j < 4; j++) d[f][j] = 0.f;

    const float* Aq = sQ + nw * PK;
    const float* Bk = sK + mw * PK;
#pragma unroll
    for (int k = 0; k < H; k += 8) {
        unsigned a[4] = {
            __float_as_uint(Aq[g * PK + k + t]),
            __float_as_uint(Aq[(g + 8) * PK + k + t]),
            __float_as_uint(Aq[g * PK + k + t + 4]),
            __float_as_uint(Aq[(g + 8) * PK + k + t + 4]) };
#pragma unroll
        for (int f = 0; f < 4; f++) {
            unsigned bb[2] = {
                __float_as_uint(Bk[(f * 8 + g) * PK + k + t]),
                __float_as_uint(Bk[(f * 8 + g) * PK + k + t + 4]) };
            mma_tf32(d[f], a, bb);
        }
    }
    // thread's elements: rows na=n0+nw+g, nb=na+8 ; cols m0+mw+f*8+2t+{0,1}
    const int na = n0 + nw + g, nb = na + 8;

    float lm = -1e30f;
    if (full) {
#pragma unroll
        for (int f = 0; f < 4; f++)
#pragma unroll
            for (int j = 0; j < 4; j++) lm = fmaxf(lm, d[f][j]);
    } else {
#pragma unroll
        for (int f = 0; f < 4; f++) {
            int c0 = m0 + mw + f * 8 + 2 * t;
            if (na < N1 && c0     < N2) lm = fmaxf(lm, d[f][0]);
            if (na < N1 && c0 + 1 < N2) lm = fmaxf(lm, d[f][1]);
            if (nb < N1 && c0     < N2) lm = fmaxf(lm, d[f][2]);
            if (nb < N1 && c0 + 1 < N2) lm = fmaxf(lm, d[f][3]);
        }
    }
    const float bm = block_max(lm, warpbuf, tid);

    float ls = 0.f;
    if (full) {
#pragma unroll
        for (int f = 0; f < 4; f++)
#pragma unroll
            for (int j = 0; j < 4; j++) {
                float p = to_tf32(__expf(d[f][j] - bm));
                d[f][j] = p; ls += p;
            }
    } else {
#pragma unroll
        for (int f = 0; f < 4; f++) {
            int c0 = m0 + mw + f * 8 + 2 * t;
            if (na < N1 && c0     < N2) { float p = to_tf32(__expf(d[f][0] - bm)); d[f][0] = p; ls += p; }
            if (na < N1 && c0 + 1 < N2) { float p = to_tf32(__expf(d[f][1] - bm)); d[f][1] = p; ls += p; }
            if (nb < N1 && c0     < N2) { float p = to_tf32(__expf(d[f][2] - bm)); d[f][2] = p; ls += p; }
            if (nb < N1 && c0 + 1 < N2) { float p = to_tf32(__expf(d[f][3] - bm)); d[f][3] = p; ls += p; }
        }
    }
    const float bs = block_sum(ls, warpbuf, tid);
    if (tid == 0) {
        int idx = (b * gridDim.y + blockIdx.y) * gridDim.x + blockIdx.x;
        mb[idx] = bm; sb[idx] = bs;
    }

    // stage tile in smem (sQ/sK dead after reductions' barriers), coalesced write
    float* sOut = smem;               // 64*65 <= 2*64*PK
    const int r0 = nw + g, r1 = r0 + 8;
#pragma unroll
    for (int f = 0; f < 4; f++) {
        int c = mw + f * 8 + 2 * t;
        sOut[r0 * 65 + c]     = d[f][0];
        sOut[r0 * 65 + c + 1] = d[f][1];
        sOut[r1 * 65 + c]     = d[f][2];
        sOut[r1 * 65 + c + 1] = d[f][3];
    }
    __syncthreads();
    if (full) {
        for (int i = tid; i < 64 * 64; i += TPB) {
            int r = i >> 6, m = i & 63;
            attn[((size_t)b * N1 + n0 + r) * N2 + m0 + m] = sOut[r * 65 + m];
        }
    } else {
        for (int i = tid; i < 64 * 64; i += TPB) {
            int r = i >> 6, m = i & 63;
            int n = n0 + r, mm = m0 + m;
            if (n < N1 && mm < N2)
                attn[((size_t)b * N1 + n) * N2 + mm] = sOut[r * 65 + m];
        }
    }
}

// ---------------- combine per-tile partials into global (M, 1/S) per batch ----------------
__global__ void softmax_reduce(const float* __restrict__ mb, const float* __restrict__ sb,
                               float* __restrict__ Ms, float* __restrict__ invS, int nb)
{
    __shared__ float red[TPB];
    const int b = blockIdx.x, tid = threadIdx.x;
    float lm = -1e30f;
    for (int i = tid; i < nb; i += TPB) lm = fmaxf(lm, mb[b * nb + i]);
    red[tid] = lm; __syncthreads();
    for (int s = 128; s; s >>= 1) { if (tid < s) red[tid] = fmaxf(red[tid], red[tid + s]); __syncthreads(); }
    const float M = red[0]; __syncthreads();
    float ls = 0.f;
    for (int i = tid; i < nb; i += TPB) ls += sb[b * nb + i] * __expf(mb[b * nb + i] - M);
    red[tid] = ls; __syncthreads();
    for (int s = 128; s; s >>= 1) { if (tid < s) red[tid] += red[tid + s]; __syncthreads(); }
    if (tid == 0) { Ms[b] = M; invS[b] = 1.f / red[0]; }
}

// ---------------- pass B: out = softmax(attn) @ K + Q  (tf32 mma) ----------------
// Double-buffered cp.async; per-tile raw mma accumulators, per-tile scale folded
// with scalar FFMAs. Warp tile: 16n x (H/2)h. sP [n][68] (a-loads bank 4g+t,
// conflict-free); sK [m][H+8] (b-loads bank 8t+g, conflict-free).
template<int H>
__global__ void __launch_bounds__(TPB)
attn_passB(const float* __restrict__ attn, const float* __restrict__ Kt,
           const float* __restrict__ Q, float* __restrict__ out,
           const float* __restrict__ mb, const float* __restrict__ Ms,
           const float* __restrict__ invS,
           int N1, int N2, int nb2)
{
    constexpr int PK = H + 8;
    constexpr int NHF = H / 16;        // h-fragments per warp (warp covers H/2 cols)
    constexpr int SPSZ = 64 * 68;
    constexpr int SKSZ = 64 * PK;
    extern __shared__ float dynB[];
    float* sPb = dynB;                 // 2 buffers of 64*68
    float* sKb = dynB + 2 * SPSZ;      // 2 buffers of 64*PK
    const int b  = blockIdx.y;
    const int n0 = blockIdx.x * 64;
    const int tid = threadIdx.x;
    const int w = tid >> 5, lane = tid & 31;
    const int g = lane >> 2, t = lane & 3;
    const int nw = (w >> 1) * 16, h0w = (w & 1) * (H / 2);
    const float M = Ms[b], iS = invS[b];

    float acc[NHF][4];
#pragma unroll
    for (int f = 0; f < NHF; f++)
#pragma unroll
        for (int j = 0; j < 4; j++) acc[f][j] = 0.f;

    auto issue_tile = [&](int jc, int buf) {
        const int m0 = jc * 64;
        float* sP = sPb + buf * SPSZ;
        float* sK = sKb + buf * SKSZ;
        for (int i = tid; i < 1024; i += TPB) {          // 64x64 attn tile
            int r = i >> 4, mq = (i & 15) * 4;
            int n = n0 + r, mm = m0 + mq;
            bool v = (n < N1) && (mm < N2);
            const float* src = attn + ((size_t)b * N1 + (v ? n : 0)) * N2 + (v ? mm : 0);
            cpa16(sP + r * 68 + mq, src, v ? 16 : 0);
        }
        for (int i = tid; i < 16 * H; i += TPB) {        // 64xH K tile
            int r = i / (H / 4), cq = (i % (H / 4)) * 4;
            bool v = (m0 + r) < N2;
            const float* src = Kt + ((size_t)b * N2 + (v ? m0 + r : 0)) * H + cq;
            cpa16(sK + r * PK + cq, src, v ? 16 : 0);
        }
        cp_commit();
    };

    issue_tile(0, 0);
    for (int jc = 0; jc < nb2; jc++) {
        const int buf = jc & 1;
        if (jc + 1 < nb2) { issue_tile(jc + 1, buf ^ 1); cp_wait<1>(); }
        else              { cp_wait<0>(); }
        __syncthreads();

        const float* sP = sPb + buf * SPSZ;
        const float* sK = sKb + buf * SKSZ;
        float dt[NHF][4];
#pragma unroll
        for (int f = 0; f < NHF; f++)
#pragma unroll
            for (int j = 0; j < 4; j++) dt[f][j] = 0.f;

#pragma unroll
        for (int m8 = 0; m8 < 64; m8 += 8) {
            unsigned a[4] = {
                __float_as_uint(sP[(nw + g) * 68 + m8 + t]),
                __float_as_uint(sP[(nw + g + 8) * 68 + m8 + t]),
                __float_as_uint(sP[(nw + g) * 68 + m8 + t + 4]),
                __float_as_uint(sP[(nw + g + 8) * 68 + m8 + t + 4]) };
#pragma unroll
            for (int f = 0; f < NHF; f++) {
                unsigned bb[2] = {
                    __float_as_uint(sK[(m8 + t) * PK + h0w + f * 8 + g]),
                    __float_as_uint(sK[(m8 + t + 4) * PK + h0w + f * 8 + g]) };
                mma_tf32(dt[f], a, bb);
            }
        }
        const float sc = __expf(mb[(b * gridDim.x + blockIdx.x) * nb2 + jc] - M) * iS;
#pragma unroll
        for (int f = 0; f < NHF; f++)
#pragma unroll
            for (int j = 0; j < 4; j++) acc[f][j] += sc * dt[f][j];
        __syncthreads();
    }

    // write: rows na=n0+nw+g, nb=na+8; cols h0w+f*8+2t+{0,1}; add fp32 Q
    const int na = n0 + nw + g, nbr = na + 8;
#pragma unroll
    for (int f = 0; f < NHF; f++) {
        int h = h0w + f * 8 + 2 * t;
        if (na < N1) {
            const size_t base = ((size_t)b * N1 + na) * H + h;
            float2 qv = *(const float2*)(Q + base);
            float2 ov = make_float2(acc[f][0] + qv.x, acc[f][1] + qv.y);
            *(float2*)(out + base) = ov;
        }
        if (nbr < N1) {
            const size_t base = ((size_t)b * N1 + nbr) * H + h;
            float2 qv = *(const float2*)(Q + base);
            float2 ov = make_float2(acc[f][2] + qv.x, acc[f][3] + qv.y);
            *(float2*)(out + base) = ov;
        }
    }
}

// ---------------- fused up2(bilinear, half-pixel, edge-clamped) + add + MLP(ReLU6) ----------------
__device__ __forceinline__ float bilin(const float* __restrict__ U, int HI, int WI, int C,
                                       int oy, int ox, int c)
{
    float sy = 0.5f * oy - 0.25f, sx = 0.5f * ox - 0.25f;
    int iy = (int)floorf(sy), ix = (int)floorf(sx);
    float fy = sy - iy, fx = sx - ix;
    int y0 = min(max(iy, 0), HI - 1), y1 = min(max(iy + 1, 0), HI - 1);
    int x0 = min(max(ix, 0), WI - 1), x1 = min(max(ix + 1, 0), WI - 1);
    float v00 = U[((size_t)y0 * WI + x0) * C + c];
    float v01 = U[((size_t)y0 * WI + x1) * C + c];
    float v10 = U[((size_t)y1 * WI + x0) * C + c];
    float v11 = U[((size_t)y1 * WI + x1) * C + c];
    return (1.f - fy) * ((1.f - fx) * v00 + fx * v01) + fy * ((1.f - fx) * v10 + fx * v11);
}

template<int CIN, int CHID, int COUT, bool HB>
__global__ void msr_kernel(const float* __restrict__ base, const float* __restrict__ up,
                           const float* __restrict__ w1, const float* __restrict__ b1,
                           const float* __restrict__ w2, const float* __restrict__ b2,
                           float* __restrict__ out, int HO, int WO)
{
    extern __shared__ float dyn[];
    float* sIn  = dyn;
    float* sHid = sIn  + 64 * (CIN + 1);
    float* sW1  = sHid + 64 * (CHID + 1);
    float* sW2  = sW1  + CIN * CHID;
    float* sB1  = sW2  + CHID * COUT;
    float* sB2  = sB1  + CHID;
    const int b   = blockIdx.y;
    const int p0  = blockIdx.x * 64;
    const int tid = threadIdx.x;
    const int HI = HO / 2, WI = WO / 2;
    for (int i = tid; i < CIN * CHID;  i += TPB) sW1[i] = w1[i];
    for (int i = tid; i < CHID * COUT; i += TPB) sW2[i] = w2[i];
    for (int i = tid; i < CHID; i += TPB) sB1[i] = b1[i];
    for (int i = tid; i < COUT; i += TPB) sB2[i] = b2[i];
    const float* U = up + (size_t)b * HI * WI * CIN;
    for (int i = tid; i < 64 * CIN; i += TPB) {
        int px = i / CIN, c = i % CIN;
        int p = p0 + px, oy = p / WO, ox = p % WO;
        float v = bilin(U, HI, WI, CIN, oy, ox, c);
        if (HB) v += base[((size_t)b * HO * WO + p) * CIN + c];
        sIn[px * (CIN + 1) + c] = v;
    }
    __syncthreads();
    for (int o = tid; o < 64 * CHID; o += TPB) {
        int px = o / CHID, h = o % CHID;
        float s = sB1[h];
#pragma unroll
        for (int c = 0; c < CIN; c++) s += sIn[px * (CIN + 1) + c] * sW1[c * CHID + h];
        sHid[px * (CHID + 1) + h] = fminf(fmaxf(s, 0.f), 6.f);
    }
    __syncthreads();
    for (int o = tid; o < 64 * COUT; o += TPB) {
        int px = o / COUT, h = o % COUT;
        float s = sB2[h];
#pragma unroll
        for (int c = 0; c < CHID; c++) s += sHid[px * (CHID + 1) + c] * sW2[c * COUT + h];
        out[((size_t)b * HO * WO + p0 + px) * COUT + h] = s;
    }
}

template<int CIN, int CHID, int COUT, bool HB>
static void launch_msr(const float* base, const float* up,
                       const float* w1, const float* b1,
                       const float* w2, const float* b2,
                       float* out, int HO, int WO)
{
    size_t smem = (size_t)(64 * (CIN + 1) + 64 * (CHID + 1) +
                           CIN * CHID + CHID * COUT + CHID + COUT) * sizeof(float);
    cudaFuncSetAttribute(msr_kernel<CIN, CHID, COUT, HB>,
                         cudaFuncAttributeMaxDynamicSharedMemorySize, (int)smem);
    dim3 grid(HO * WO / 64, 2);
    msr_kernel<CIN, CHID, COUT, HB><<<grid, TPB, smem>>>(base, up, w1, b1, w2, b2, out, HO, WO);
}

// ---------------- one CSA stage ----------------
template<int H>
static void run_csa(const float* q_fp, const float* q_t, const float* k_t, float* outcl,
                    float* attn, float* mb, float* sb, float* Ms, float* invS,
                    int N1, int N2)
{
    int nb1 = (N1 + 63) / 64, nb2 = (N2 + 63) / 64;
    attn_passA<H><<<dim3(nb2, nb1, 2), TPB>>>(q_t, k_t, attn, mb, sb, N1, N2);
    softmax_reduce<<<2, TPB>>>(mb, sb, Ms, invS, nb1 * nb2);
    size_t smemB = (size_t)(2 * 64 * 68 + 2 * 64 * (H + 8)) * sizeof(float);
    cudaFuncSetAttribute(attn_passB<H>,
                         cudaFuncAttributeMaxDynamicSharedMemorySize, (int)smemB);
    attn_passB<H><<<dim3(nb1, 2), TPB, smemB>>>(attn, k_t, q_fp, outcl, mb, Ms, invS, N1, N2, nb2);
}

extern "C" void kernel_launch(void* const* d_in, const int* in_sizes, int n_in,
                              void* d_out, int out_size)
{
    const float* f0   = (const float*)d_in[0];
    const float* f1   = (const float*)d_in[1];
    const float* f2   = (const float*)d_in[2];
    const float* f3   = (const float*)d_in[3];
    const float* c1w1 = (const float*)d_in[4];
    const float* c1w2 = (const float*)d_in[5];
    const float* c2w1 = (const float*)d_in[6];
    const float* c2w2 = (const float*)d_in[7];
    const float* c3w1 = (const float*)d_in[8];
    const float* c3w2 = (const float*)d_in[9];
    const float* m1w1 = (const float*)d_in[10];
    const float* m1b1 = (const float*)d_in[11];
    const float* m1w2 = (const float*)d_in[12];
    const float* m1b2 = (const float*)d_in[13];
    const float* m2w1 = (const float*)d_in[14];
    const float* m2b1 = (const float*)d_in[15];
    const float* m2w2 = (const float*)d_in[16];
    const float* m2b2 = (const float*)d_in[17];
    const float* m3w1 = (const float*)d_in[18];
    const float* m3b1 = (const float*)d_in[19];
    const float* m3w2 = (const float*)d_in[20];
    const float* m3b2 = (const float*)d_in[21];
    const float* m4w1 = (const float*)d_in[22];
    const float* m4b1 = (const float*)d_in[23];
    const float* m4w2 = (const float*)d_in[24];
    const float* m4b2 = (const float*)d_in[25];
    float* outp = (float*)d_out;

    float *attn, *q, *qt, *kv, *kvt, *x1, *x2, *x3, *y1, *y2, *y3, *mb, *sb, *Ms, *invS;
    cudaGetSymbolAddress((void**)&attn, g_attn);
    cudaGetSymbolAddress((void**)&q,    g_q);
    cudaGetSymbolAddress((void**)&qt,   g_qt);
    cudaGetSymbolAddress((void**)&kv,   g_kv);
    cudaGetSymbolAddress((void**)&kvt,  g_kvt);
    cudaGetSymbolAddress((void**)&x1,   g_x1);
    cudaGetSymbolAddress((void**)&x2,   g_x2);
    cudaGetSymbolAddress((void**)&x3,   g_x3);
    cudaGetSymbolAddress((void**)&y1,   g_y1);
    cudaGetSymbolAddress((void**)&y2,   g_y2);
    cudaGetSymbolAddress((void**)&y3,   g_y3);
    cudaGetSymbolAddress((void**)&mb,   g_mb);
    cudaGetSymbolAddress((void**)&sb,   g_sb);
    cudaGetSymbolAddress((void**)&Ms,   g_Ms);
    cudaGetSymbolAddress((void**)&invS, g_invS);

    // ---- CSA stage 1: hr=f1 [2,128,28,28] N1=784, lr=f0 [2,160,14,14] N2=196, H=64
    proj_kernel<false><<<dim3(13, 2), TPB>>>(f1, c1w1, q,  qt,  784, 128, 64);
    proj_kernel<false><<<dim3(4,  2), TPB>>>(f0, c1w2, kv, kvt, 196, 160, 64);
    run_csa<64>(q, qt, kvt, x1, attn, mb, sb, Ms, invS, 784, 196);

    // ---- CSA stage 2: hr=f2 [2,64,56,56] N1=3136, lr=x1 [2,784,64] N2=784, H=64
    proj_kernel<false><<<dim3(49, 2), TPB>>>(f2, c2w1, q,  qt,  3136, 64, 64);
    proj_kernel<true ><<<dim3(13, 2), TPB>>>(x1, c2w2, kv, kvt, 784,  64, 64);
    run_csa<64>(q, qt, kvt, x2, attn, mb, sb, Ms, invS, 3136, 784);

    // ---- CSA stage 3: hr=f3 [2,32,112,112] N1=12544, lr=x2 [2,3136,64] N2=3136, H=32
    proj_kernel<false><<<dim3(196, 2), TPB>>>(f3, c3w1, q,  qt,  12544, 32, 32);
    proj_kernel<true ><<<dim3(49,  2), TPB>>>(x2, c3w2, kv, kvt, 3136,  64, 32);
    run_csa<32>(q, qt, kvt, x3, attn, mb, sb, Ms, invS, 12544, 3136);

    // ---- MSR pyramid (fused up2 + add + MLP/ReLU6), all channel-last
    launch_msr<64, 64, 32, true >(x2, x1, m1w1, m1b1, m1w2, m1b2, y1,  56,  56);
    launch_msr<32, 32, 16, true >(x3, y1, m2w1, m2b1, m2w2, m2b2, y2, 112, 112);
    launch_msr<16, 16, 8,  false>(0,  y2, m3w1, m3b1, m3w2, m3b2, y3, 224, 224);
    launch_msr<8,  2,  1,  false>(0,  y3, m4w1, m4b1, m4w2, m4b2, outp, 448, 448);
    (void)in_sizes; (void)n_in; (void)out_size;
}